// round 16
// baseline (speedup 1.0000x reference)
#include <cuda_runtime.h>
#include <cuda_fp16.h>
#include <cstdint>

// ---------------- problem constants ----------------
#define Nn   2048
#define Bb   16
#define Cc   64
#define Tt   12
#define Ee   10
#define Oo   64
#define MC   (Bb*Cc*Tt)        // 12288
#define NT   (Nn*Tt)           // 24576
#define ONT  (Oo*Nn*Tt)        // 1572864
#define XAV_SIZE (Bb*ONT)      // 25165824 floats

#define TILE_WORDS 131072      // 256*512 (tiled packed-half operand layout)

// ---------------- scratch (device globals) ----------------
__device__ uint32_t g_Ah  [(size_t)16*TILE_WORDS];   // A tiled-packed
__device__ uint32_t g_PTh [(size_t)16*TILE_WORDS];
__device__ uint32_t g_hXr [(size_t)96*TILE_WORDS];   // B tiled-packed
__device__ uint32_t g_hG1 [(size_t)96*TILE_WORDS];
__device__ uint32_t g_hD1 [(size_t)96*TILE_WORDS];
__device__ __half   g_Xh [(size_t)Nn*MC];            // half row-major [node][col]
__device__ __half   g_G1h[(size_t)Nn*MC];
__device__ __half   g_G2h[(size_t)Nn*MC];
__device__ __half   g_D1h[(size_t)Nn*MC];
__device__ __half   g_D2h[(size_t)Nn*MC];

// ---------------- helpers ----------------
__device__ __forceinline__ uint32_t smem_u32(const void* p){
    uint32_t a;
    asm("{ .reg .u64 t; cvta.to.shared.u64 t, %1; cvt.u32.u64 %0, t; }" : "=r"(a) : "l"(p));
    return a;
}
__device__ __forceinline__ void mma_f16(float* d,
    uint32_t a0, uint32_t a1, uint32_t a2, uint32_t a3,
    uint32_t b0, uint32_t b1)
{
    asm volatile(
        "mma.sync.aligned.m16n8k16.row.col.f32.f16.f16.f32 "
        "{%0,%1,%2,%3}, {%4,%5,%6,%7}, {%8,%9}, {%0,%1,%2,%3};"
        : "+f"(d[0]), "+f"(d[1]), "+f"(d[2]), "+f"(d[3])
        : "r"(a0), "r"(a1), "r"(a2), "r"(a3), "r"(b0), "r"(b1));
}
__device__ __forceinline__ void ldmat4(uint32_t* r, uint32_t addr){
    asm volatile(
        "ldmatrix.sync.aligned.m8n8.x4.shared.b16 {%0,%1,%2,%3}, [%4];"
        : "=r"(r[0]), "=r"(r[1]), "=r"(r[2]), "=r"(r[3]) : "r"(addr));
}
__device__ __forceinline__ void ldmat4t(uint32_t* r, uint32_t addr){
    asm volatile(
        "ldmatrix.sync.aligned.m8n8.x4.trans.shared.b16 {%0,%1,%2,%3}, [%4];"
        : "=r"(r[0]), "=r"(r[1]), "=r"(r[2]), "=r"(r[3]) : "r"(addr));
}
__device__ __forceinline__ void cp16(uint32_t d, const void* s){
    asm volatile("cp.async.cg.shared.global [%0], [%1], 16;" :: "r"(d), "l"(s));
}
#define CP_COMMIT() asm volatile("cp.async.commit_group;" ::: "memory")
#define CP_WAIT1()  asm volatile("cp.async.wait_group 1;" ::: "memory")

__device__ __forceinline__ uint32_t pack2h(float lo, float hi){
    __half2 h = __floats2half2_rn(lo, hi);
    return *reinterpret_cast<uint32_t*>(&h);
}

// ---------------- A = rowsoftmax(relu(E E^T)) -> tiled packed half ----------------
__global__ __launch_bounds__(256) void compute_A_kernel(const float* __restrict__ emb)
{
    __shared__ float row[Nn];
    __shared__ float red[256];
    const int n = blockIdx.x, tid = threadIdx.x;
    float e[Ee];
#pragma unroll
    for (int d = 0; d < Ee; d++) e[d] = emb[n*Ee + d];
    float lmax = -1e30f;
    for (int m = tid; m < Nn; m += 256){
        float s = 0.f;
#pragma unroll
        for (int d = 0; d < Ee; d++) s += e[d] * emb[m*Ee + d];
        s = fmaxf(s, 0.f);
        row[m] = s; lmax = fmaxf(lmax, s);
    }
    red[tid] = lmax; __syncthreads();
    for (int s = 128; s > 0; s >>= 1){ if (tid < s) red[tid] = fmaxf(red[tid], red[tid+s]); __syncthreads(); }
    const float mx = red[0]; __syncthreads();
    float lsum = 0.f;
    for (int m = tid; m < Nn; m += 256){ float v = expf(row[m] - mx); row[m] = v; lsum += v; }
    red[tid] = lsum; __syncthreads();
    for (int s = 128; s > 0; s >>= 1){ if (tid < s) red[tid] += red[tid+s]; __syncthreads(); }
    const float inv = 1.f / red[0];
    const size_t base = ((size_t)(n >> 7)*256)*512 + (size_t)(n & 127)*4;
    for (int i = tid; i < 1024; i += 256){
        uint32_t w = pack2h(row[2*i]*inv, row[2*i+1]*inv);
        g_Ah[base + (size_t)(i >> 2)*512 + (i & 3)] = w;
    }
}

// ---- x[B,C,N,T] -> Xh half row-major [n][bc*12+t] + hXr tiled packed ----
__global__ __launch_bounds__(256) void transpose_X_kernel(const float* __restrict__ x)
{
    const int g  = blockIdx.x * 256 + threadIdx.x;
    const int bc = g >> 10;
    const int np = g & 1023;
    const int n0 = np*2;
    const float4* s0 = (const float4*)(x + ((size_t)bc*Nn + n0    ) * Tt);
    const float4* s1 = (const float4*)(x + ((size_t)bc*Nn + n0 + 1) * Tt);
    float4 a0 = s0[0], a1 = s0[1], a2 = s0[2];
    float4 b0 = s1[0], b1 = s1[1], b2 = s1[2];
    float av[12] = {a0.x,a0.y,a0.z,a0.w, a1.x,a1.y,a1.z,a1.w, a2.x,a2.y,a2.z,a2.w};
    float bv[12] = {b0.x,b0.y,b0.z,b0.w, b1.x,b1.y,b1.z,b1.w, b2.x,b2.y,b2.z,b2.w};
    uint2* d0 = (uint2*)(g_Xh + (size_t)n0*MC + (size_t)bc*Tt);
    uint2* d1 = (uint2*)(g_Xh + (size_t)(n0+1)*MC + (size_t)bc*Tt);
    d0[0] = make_uint2(pack2h(av[0],av[1]),  pack2h(av[2],av[3]));
    d0[1] = make_uint2(pack2h(av[4],av[5]),  pack2h(av[6],av[7]));
    d0[2] = make_uint2(pack2h(av[8],av[9]),  pack2h(av[10],av[11]));
    d1[0] = make_uint2(pack2h(bv[0],bv[1]),  pack2h(bv[2],bv[3]));
    d1[1] = make_uint2(pack2h(bv[4],bv[5]),  pack2h(bv[6],bv[7]));
    d1[2] = make_uint2(pack2h(bv[8],bv[9]),  pack2h(bv[10],bv[11]));
    const size_t koff = (size_t)(np >> 2)*512 + (np & 3);
#pragma unroll
    for (int t = 0; t < 12; t++){
        const int col = bc*12 + t;
        g_hXr[((size_t)(col >> 7)*256)*512 + koff + (size_t)(col & 127)*4] = pack2h(av[t], bv[t]);
    }
}

// ---------------- PTh tiled packed: PT[m][k] = support[k][m] ----------------
__global__ void transpose2k_kernel(const float* __restrict__ S, uint32_t* __restrict__ D)
{
    __shared__ float tile[32][33];
    const int x0 = blockIdx.x*32, y0 = blockIdx.y*32;
    const int tx = threadIdx.x, ty = threadIdx.y;       // (32,8)
#pragma unroll
    for (int j = 0; j < 4; j++)
        tile[ty + j*8][tx] = S[(size_t)(y0 + ty + j*8)*Nn + x0 + tx];
    __syncthreads();
    const int m = x0 + tx;
    const size_t mb = ((size_t)(m >> 7)*256)*512 + (size_t)(m & 127)*4;
#pragma unroll
    for (int j = 0; j < 2; j++){
        const int p = ty + j*8;
        const int i = (y0 >> 1) + p;
        D[mb + (size_t)(i >> 2)*512 + (i & 3)] = pack2h(tile[2*p][tx], tile[2*p+1][tx]);
    }
}

// ---------------- fp16 mma.sync GEMM, 6-stage cp.async, paired k-tiles ----------------
#define STAGE_BYTES 16384
#define GEMM_SMEM (6*STAGE_BYTES)   // 98304

__global__ __launch_bounds__(256, 2) void mma_gemm(
    int Ncols, float alpha,
    const uint32_t* __restrict__ At,
    const uint32_t* __restrict__ Bt,
    __half* __restrict__ Ch,
    const __half* __restrict__ ResH, float beta,
    uint32_t* __restrict__ hOut)
{
    extern __shared__ __align__(16) uint32_t smw[];
    const uint32_t sbase = smem_u32(smw);

    const int tid  = threadIdx.x;
    const int lane = tid & 31;
    const int wid  = tid >> 5;
    const int wm   = wid >> 1;
    const int wn   = wid & 1;
    const int gy   = lane >> 2;
    const int gx   = lane & 3;
    const int mat  = lane >> 3;
    const int mr   = lane & 7;

    const int nBase = blockIdx.x * 128;
    const int mBase = blockIdx.y * 128;

    const uint32_t* aG = At + (size_t)blockIdx.y*TILE_WORDS + tid*8;
    const uint32_t* bG = Bt + (size_t)blockIdx.x*TILE_WORDS + tid*8;

    const uint32_t aAddr0 = (uint32_t)((wm*32 + (mat & 1)*8 + mr)*16 + (mat >> 1)*2048);
    const uint32_t aAddr1 = aAddr0 + 256;
    uint32_t bAddr[4];
#pragma unroll
    for (int q = 0; q < 4; q++)
        bAddr[q] = 8192 + (uint32_t)((wn*64 + q*16 + (mat >> 1)*8 + mr)*16 + (mat & 1)*2048);

#define ISSUE_AT(kt_, st_) do { \
        uint32_t sb_ = sbase + (uint32_t)(st_) * STAGE_BYTES; \
        const uint32_t* as_ = aG + (size_t)(kt_)*2048; \
        const uint32_t* bs_ = bG + (size_t)(kt_)*2048; \
        cp16(sb_ + tid*32,           as_); \
        cp16(sb_ + tid*32 + 16,      as_ + 4); \
        cp16(sb_ + 8192 + tid*32,    bs_); \
        cp16(sb_ + 8192 + tid*32+16, bs_ + 4); \
    } while(0)

    float acc[2][8][4];
#pragma unroll
    for (int mt = 0; mt < 2; mt++)
#pragma unroll
        for (int nt = 0; nt < 8; nt++)
#pragma unroll
            for (int r = 0; r < 4; r++) acc[mt][nt][r] = 0.f;

#define COMPUTE_TILE(so_) do { \
        _Pragma("unroll") \
        for (int ks = 0; ks < 2; ks++){ \
            uint32_t a0[4], a1[4]; \
            ldmat4(a0, (so_) + aAddr0 + ks*4096); \
            ldmat4(a1, (so_) + aAddr1 + ks*4096); \
            uint32_t bb[4][4]; \
            ldmat4(bb[0], (so_) + bAddr[0] + ks*4096); \
            ldmat4(bb[1], (so_) + bAddr[1] + ks*4096); \
            ldmat4(bb[2], (so_) + bAddr[2] + ks*4096); \
            ldmat4(bb[3], (so_) + bAddr[3] + ks*4096); \
            _Pragma("unroll") \
            for (int nt = 0; nt < 8; nt++){ \
                const uint32_t b0 = bb[nt >> 1][(nt & 1)*2]; \
                const uint32_t b1 = bb[nt >> 1][(nt & 1)*2 + 1]; \
                mma_f16(acc[0][nt], a0[0], a0[1], a0[2], a0[3], b0, b1); \
                mma_f16(acc[1][nt], a1[0], a1[1], a1[2], a1[3], b0, b1); \
            } \
        } \
    } while(0)

    // prologue: pairs 0 and 1
    ISSUE_AT(0, 0); ISSUE_AT(1, 1); CP_COMMIT();
    ISSUE_AT(2, 2); ISSUE_AT(3, 3); CP_COMMIT();

    int s0 = 0;
    for (int p = 0; p < 32; p++){
        CP_WAIT1();
        __syncthreads();
        if (p < 30){
            const int si = (s0 >= 2) ? (s0 - 2) : (s0 + 4);   // (s0+4)%6
            ISSUE_AT(2*p + 4, si);
            ISSUE_AT(2*p + 5, si + 1);
        }
        CP_COMMIT();
        const uint32_t soA = sbase + (uint32_t)s0 * STAGE_BYTES;
        COMPUTE_TILE(soA);
        COMPUTE_TILE(soA + STAGE_BYTES);
        s0 += 2; if (s0 == 6) s0 = 0;
    }
#undef ISSUE_AT
#undef COMPUTE_TILE

#pragma unroll
    for (int mt = 0; mt < 2; mt++){
#pragma unroll
        for (int nt = 0; nt < 8; nt++){
            const int row0 = mBase + wm*32 + mt*16 + gy;
            const int col0 = nBase + wn*64 + nt*8 + gx*2;
            float v0 = acc[mt][nt][0] * alpha;
            float v1 = acc[mt][nt][1] * alpha;
            float v2 = acc[mt][nt][2] * alpha;
            float v3 = acc[mt][nt][3] * alpha;
            if (ResH){
                __half2 r0 = *(const __half2*)(ResH + (size_t)row0    *Ncols + col0);
                __half2 r1 = *(const __half2*)(ResH + (size_t)(row0+8)*Ncols + col0);
                float2 f0 = __half22float2(r0), f1 = __half22float2(r1);
                v0 += beta * f0.x; v1 += beta * f0.y;
                v2 += beta * f1.x; v3 += beta * f1.y;
            }
            *(__half2*)(Ch + (size_t)row0    *Ncols + col0) = __floats2half2_rn(v0, v1);
            *(__half2*)(Ch + (size_t)(row0+8)*Ncols + col0) = __floats2half2_rn(v2, v3);
            if (hOut){
                float p0 = __shfl_xor_sync(0xffffffffu, v0, 4);
                float p1 = __shfl_xor_sync(0xffffffffu, v1, 4);
                float p2 = __shfl_xor_sync(0xffffffffu, v2, 4);
                float p3 = __shfl_xor_sync(0xffffffffu, v3, 4);
                if (!(gy & 1)){
                    const int kp = row0 >> 1;
                    const size_t cb0 = ((size_t)(col0 >> 7)*256)*512 + (size_t)(col0 & 127)*4;
                    const size_t cb1 = ((size_t)((col0+1) >> 7)*256)*512 + (size_t)((col0+1) & 127)*4;
                    const size_t k0 = (size_t)(kp >> 2)*512 + (kp & 3);
                    const size_t k1 = k0 + 512;
                    hOut[cb0 + k0] = pack2h(v0, p0);
                    hOut[cb1 + k0] = pack2h(v1, p1);
                    hOut[cb0 + k1] = pack2h(v2, p2);
                    hOut[cb1 + k1] = pack2h(v3, p3);
                }
            }
        }
    }
}

// ---------------- fused per-node epilogue via tensor cores (both modes) ----------------
#define KS 200
#define WS 72
#define OS 72
#define SA_BYTES   (192*KS*2)            // 76800
#define SW_BYTES   (192*WS*2)            // 27648
#define SB_OFF     (SA_BYTES + SW_BYTES) // 104448
#define SOUT_OFF   (SB_OFF + 256)        // 104704
#define EPI_SMEM   (SOUT_OFF + 192*OS*4) // 160000

__global__ __launch_bounds__(512) void epilogue_kernel(
    const float* __restrict__ emb,
    const float* __restrict__ wpool,
    const float* __restrict__ bpool,
    const float* __restrict__ mlp_w,
    const float* __restrict__ mlp_b,
    float* __restrict__ out)
{
    extern __shared__ __align__(16) char smc[];
    __half* sA   = (__half*)smc;
    __half* sW   = (__half*)(smc + SA_BYTES);
    float*  sB   = (float*)(smc + SB_OFF);
    float*  sOut = (float*)(smc + SOUT_OFF);
    const int n = blockIdx.x, tid = threadIdx.x;

    float e[Ee];
#pragma unroll
    for (int d = 0; d < Ee; d++) e[d] = emb[n*Ee + d];

    // fill s=0 segment (Xh) once
    {
        const __half* s0 = g_Xh + (size_t)n*MC;
        for (int rem = tid; rem < 1024; rem += 512){
            const int b = rem >> 6, c = rem & 63;
            const __half* src = s0 + b*768 + c*12;
            uint2 q0 = ((const uint2*)src)[0];
            uint2 q1 = ((const uint2*)src)[1];
            uint2 q2 = ((const uint2*)src)[2];
            uint32_t w[6] = {q0.x, q0.y, q1.x, q1.y, q2.x, q2.y};
            __half* dst = sA + (b*12)*KS + c;
#pragma unroll
            for (int j = 0; j < 6; j++){
                __half2 hh = *(__half2*)&w[j];
                dst[(2*j  )*KS] = __low2half(hh);
                dst[(2*j+1)*KS] = __high2half(hh);
            }
        }
    }

    const int warp = tid >> 5, lane = tid & 31;
    const int mw = warp >> 2, nw = warp & 3;
    const int grp = lane >> 3, lr = lane & 7;
    const int gy = lane >> 2, gx = lane & 3;

    uint32_t aOff[3];
#pragma unroll
    for (int mt = 0; mt < 3; mt++)
        aOff[mt] = smem_u32(sA + (mw*48 + mt*16 + (grp & 1)*8 + lr)*KS) + (grp >> 1)*16;
    const uint32_t bOff = smem_u32(sW + ((grp & 1)*8 + lr)*WS + nw*16 + (grp >> 1)*8);

    for (int mode = 0; mode < 2; mode++){
        const __half* s1 = ((mode == 0) ? g_G1h : g_D1h) + (size_t)n*MC;
        const __half* s2 = ((mode == 0) ? g_G2h : g_D2h) + (size_t)n*MC;

        // fill segments s=1,2
        for (int u = tid; u < 2048; u += 512){
            const int s = 1 + (u >> 10);
            const int rem = u & 1023;
            const int b = rem >> 6, c = rem & 63;
            const __half* src = (s == 1 ? s1 : s2) + b*768 + c*12;
            uint2 q0 = ((const uint2*)src)[0];
            uint2 q1 = ((const uint2*)src)[1];
            uint2 q2 = ((const uint2*)src)[2];
            uint32_t w[6] = {q0.x, q0.y, q1.x, q1.y, q2.x, q2.y};
            __half* dst = sA + (b*12)*KS + s*64 + c;
#pragma unroll
            for (int j = 0; j < 6; j++){
                __half2 hh = *(__half2*)&w[j];
                dst[(2*j  )*KS] = __low2half(hh);
                dst[(2*j+1)*KS] = __high2half(hh);
            }
        }
        // fill sW, sB
        if (mode == 0){
            for (int i = tid; i < 12288; i += 512){
                float s = 0.f;
#pragma unroll
                for (int d = 0; d < Ee; d++) s += e[d] * wpool[d*12288 + i];
                sW[(i >> 6)*WS + (i & 63)] = __float2half(s);
            }
            if (tid < Oo){
                float s = 0.f;
#pragma unroll
                for (int d = 0; d < Ee; d++) s += e[d] * bpool[d*Oo + tid];
                sB[tid] = s;
            }
        } else {
            for (int i = tid; i < 12288; i += 512)
                sW[(i >> 6)*WS + (i & 63)] = __float2half(mlp_w[i]);
            if (tid < Oo) sB[tid] = mlp_b[tid];
        }
        __syncthreads();

        float acc[3][2][4];
#pragma unroll
        for (int mt = 0; mt < 3; mt++)
#pragma unroll
            for (int nt = 0; nt < 2; nt++)
#pragma unroll
                for (int r = 0; r < 4; r++) acc[mt][nt][r] = 0.f;

#pragma unroll
        for (int ks = 0; ks < 12; ks++){
            uint32_t bf[4];
            ldmat4t(bf, bOff + ks*(16*WS*2));
#pragma unroll
            for (int mt = 0; mt < 3; mt++){
                uint32_t af[4];
                ldmat4(af, aOff[mt] + ks*32);
                mma_f16(acc[mt][0], af[0], af[1], af[2], af[3], bf[0], bf[1]);
                mma_f16(acc[mt][1], af[0], af[1], af[2], af[3], bf[2], bf[3]);
            }
        }

#pragma unroll
        for (int mt = 0; mt < 3; mt++){
#pragma unroll
            for (int nt = 0; nt < 2; nt++){
                const int r0 = mw*48 + mt*16 + gy;
                const int cb = nw*16 + nt*8 + gx*2;
                *(float2*)(sOut + r0*OS + cb)     = make_float2(acc[mt][nt][0], acc[mt][nt][1]);
                *(float2*)(sOut + (r0+8)*OS + cb) = make_float2(acc[mt][nt][2], acc[mt][nt][3]);
            }
        }
        __syncthreads();

        float* outBase = out + (mode ? (size_t)XAV_SIZE : 0);
        for (int u = tid; u < 1024; u += 512){
            const int b = u >> 6, o = u & 63;
            const float bia = sB[o];
            float v[12];
#pragma unroll
            for (int t = 0; t < 12; t++) v[t] = sOut[(b*12 + t)*OS + o] + bia;
            float4* op = (float4*)(outBase + (size_t)b*ONT + (size_t)o*NT + (size_t)n*Tt);
            op[0] = make_float4(v[0], v[1], v[2],  v[3]);
            op[1] = make_float4(v[4], v[5], v[6],  v[7]);
            op[2] = make_float4(v[8], v[9], v[10], v[11]);
        }
        if (mode == 0) __syncthreads();   // protect sA/sW/sOut before mode-1 refill
    }
}

// ---------------- launch ----------------
extern "C" void kernel_launch(void* const* d_in, const int* in_sizes, int n_in,
                              void* d_out, int out_size)
{
    const float* x     = (const float*)d_in[0];
    const float* emb   = (const float*)d_in[1];
    const float* sup   = (const float*)d_in[2];
    const float* wpool = (const float*)d_in[3];
    const float* bpool = (const float*)d_in[4];
    const float* mlp_w = (const float*)d_in[5];
    const float* mlp_b = (const float*)d_in[6];
    float* out = (float*)d_out;

    cudaFuncSetAttribute(epilogue_kernel, cudaFuncAttributeMaxDynamicSharedMemorySize, EPI_SMEM);
    cudaFuncSetAttribute(mma_gemm, cudaFuncAttributeMaxDynamicSharedMemorySize, GEMM_SMEM);

    uint32_t *pAh, *pPTh, *phXr, *phG1, *phD1;
    __half *pXh, *pG1h, *pG2h, *pD1h, *pD2h;
    cudaGetSymbolAddress((void**)&pAh,  g_Ah);
    cudaGetSymbolAddress((void**)&pPTh, g_PTh);
    cudaGetSymbolAddress((void**)&phXr, g_hXr);
    cudaGetSymbolAddress((void**)&phG1, g_hG1);
    cudaGetSymbolAddress((void**)&phD1, g_hD1);
    cudaGetSymbolAddress((void**)&pXh,  g_Xh);
    cudaGetSymbolAddress((void**)&pG1h, g_G1h);
    cudaGetSymbolAddress((void**)&pG2h, g_G2h);
    cudaGetSymbolAddress((void**)&pD1h, g_D1h);
    cudaGetSymbolAddress((void**)&pD2h, g_D2h);

    // precompute
    compute_A_kernel<<<Nn, 256>>>(emb);
    transpose_X_kernel<<<4096, 256>>>(x);
    transpose2k_kernel<<<dim3(Nn/32, Nn/32), dim3(32, 8)>>>(sup, pPTh);

    // big GEMMs [2048 x 12288]
    dim3 gBig(MC/128, 16);
    // G1 = A @ X
    mma_gemm<<<gBig, 256, GEMM_SMEM>>>(MC, 1.f, pAh, phXr, pG1h, nullptr, 0.f, phG1);
    // G2 = 2*A @ G1 - X
    mma_gemm<<<gBig, 256, GEMM_SMEM>>>(MC, 2.f, pAh, phG1, pG2h, pXh, -1.f, nullptr);
    // D1 = PT @ X
    mma_gemm<<<gBig, 256, GEMM_SMEM>>>(MC, 1.f, pPTh, phXr, pD1h, nullptr, 0.f, phD1);
    // D2 = PT @ D1
    mma_gemm<<<gBig, 256, GEMM_SMEM>>>(MC, 1.f, pPTh, phD1, pD2h, nullptr, 0.f, nullptr);

    // fused epilogue (both outputs)
    epilogue_kernel<<<Nn, 512, EPI_SMEM>>>(emb, wpool, bpool, mlp_w, mlp_b, out);
}